// round 15
// baseline (speedup 1.0000x reference)
#include <cuda_runtime.h>
#include <cuda_bf16.h>
#include <cstdint>
#include <math.h>

// ---------------------------------------------------------------------------
// Binary CNN fully fused. Round 15: shared-window dual-channel stage C.
//  - stage C: warps 0,1 -> h rows 0..2; warps 2,3 -> rows 3..5. Each lane
//    computes TWO channels (c, c+64) sharing ONE 12-word sliding window:
//    2 independent chains at +12 regs instead of +24.
//  - stage B: 3-row interleave (3 chains), stage D: 16 accumulators.
//  - __launch_bounds__(128, 9): <=56 regs, 9 blocks/SM.
// Per-sample numerics identical to rounds 5-14 (rel_err == 0.0).
// ---------------------------------------------------------------------------

#define EPSBND 1e-5
#define BAND   1e-3f

__device__ float    g_w1s[32 * 9];
__device__ double   g_inv1d[32], g_bz1d[32];
__device__ double   g_b1d[32];
__device__ float2   g_p1[32];
__device__ __align__(16) unsigned g_wb2[64 * 4];   // sign-folded
__device__ int2     g_kB[64];                 // (K96, K64)
__device__ __align__(16) unsigned g_wb3[128 * 8];  // sign-folded
__device__ int2     g_kC[128];                // (K192, K128)
__device__ unsigned g_wb4t[24 * 128];         // [(h*4+j)*128 + c], sign-folded
__device__ int      g_kD[128];                // K768
__device__ unsigned g_wfb[10 * 64];

__device__ __forceinline__ float bnref(float dv, float bias, float inv, float bz) {
    return __fadd_rn(__fmul_rn(__fadd_rn(dv, bias), inv), bz);
}

__device__ void mk_k(float b, float g, float be, float m, float v,
                     int C0, int C1, int* K0, int* K1)
{
    float inv = __fmul_rn(g, rsqrtf(__fadd_rn(v, 1e-5f)));
    float bz  = __fsub_rn(be, __fmul_rn(m, inv));

    if (inv > 0.0f) {
        int lo = -1025, hi = 1025, ans = 1 << 20;
        while (lo <= hi) {
            int mid = lo + ((hi - lo) >> 1);
            if (bnref((float)mid, b, inv, bz) >= 0.0f) { ans = mid; hi = mid - 1; }
            else lo = mid + 1;
        }
        *K0 = (C0 - ans) >> 1;
        *K1 = (C1 - ans) >> 1;
    } else if (inv < 0.0f) {
        int lo = -1025, hi = 1025, ans = -(1 << 20);
        while (lo <= hi) {
            int mid = lo + ((hi - lo) >> 1);
            if (bnref((float)mid, b, inv, bz) >= 0.0f) { ans = mid; lo = mid + 1; }
            else hi = mid - 1;
        }
        *K0 = (C0 + ans) >> 1;
        *K1 = (C1 + ans) >> 1;
    } else {
        bool always = (bz >= 0.0f);
        *K0 = always ? C0 : -1;
        *K1 = always ? C1 : -1;
    }
}

__global__ void prep_kernel(
    const float* __restrict__ w1, const float* __restrict__ b1,
    const float* __restrict__ w2, const float* __restrict__ b2,
    const float* __restrict__ w3, const float* __restrict__ b3,
    const float* __restrict__ w4, const float* __restrict__ b4,
    const float* __restrict__ g1, const float* __restrict__ be1,
    const float* __restrict__ m1, const float* __restrict__ v1,
    const float* __restrict__ g2, const float* __restrict__ be2,
    const float* __restrict__ m2, const float* __restrict__ v2,
    const float* __restrict__ g3, const float* __restrict__ be3,
    const float* __restrict__ m3, const float* __restrict__ v3,
    const float* __restrict__ g4, const float* __restrict__ be4,
    const float* __restrict__ m4, const float* __restrict__ v4,
    const float* __restrict__ wf)
{
    int u = blockIdx.x * blockDim.x + threadIdx.x;

    if (u < 288) {
        g_w1s[u] = (w1[u] >= 0.f) ? 1.f : -1.f;
        return;
    }
    u -= 288;
    if (u < 32) {
        int c = u;
        double inv = (double)g1[c] / sqrt((double)v1[c] + EPSBND);
        double bz  = (double)be1[c] - (double)m1[c] * inv;
        g_inv1d[c] = inv;
        g_bz1d[c]  = bz;
        g_b1d[c]   = (double)b1[c];
        g_p1[c]    = make_float2((float)inv, (float)((double)b1[c] * inv + bz));
        return;
    }
    u -= 32;
    if (u < 320) {
        if (u < 64) {
            int K0, K1;
            mk_k(b2[u], g2[u], be2[u], m2[u], v2[u], 96, 64, &K0, &K1);
            g_kB[u] = make_int2(K0, K1);
        } else if (u < 192) {
            int c = u - 64, K0, K1;
            mk_k(b3[c], g3[c], be3[c], m3[c], v3[c], 192, 128, &K0, &K1);
            g_kC[c] = make_int2(K0, K1);
        } else {
            int c = u - 192, K0, K1;
            mk_k(b4[c], g4[c], be4[c], m4[c], v4[c], 768, 768, &K0, &K1);
            g_kD[c] = K0;
        }
        return;
    }
    u -= 320;
    if (u < 256) {
        int c = u >> 2, t = u & 3;
        unsigned flip = (g2[c] < 0.f) ? 0xffffffffu : 0u;
        unsigned word = 0;
        if (t < 3) {
            for (int i = 0; i < 32; i++)
                word |= (unsigned)(w2[c * 96 + i * 3 + t] >= 0.f) << i;
            word ^= flip;
        }
        g_wb2[u] = word;
        return;
    }
    u -= 256;
    if (u < 1024) {
        int c = u >> 3, r = u & 7;
        unsigned flip = (g3[c] < 0.f) ? 0xffffffffu : 0u;
        unsigned word = 0;
        if (r < 6) {
            int t = r >> 1, j = r & 1;
            for (int i = 0; i < 32; i++) {
                int cin = j * 32 + i;
                word |= (unsigned)(w3[c * 192 + cin * 3 + t] >= 0.f) << i;
            }
            word ^= flip;
        }
        g_wb3[u] = word;
        return;
    }
    u -= 1024;
    if (u < 3072) {
        int c = u / 24, r = u % 24, h = r >> 2, j = r & 3;
        unsigned flip = (g4[c] < 0.f) ? 0xffffffffu : 0u;
        unsigned word = 0;
        for (int i = 0; i < 32; i++) {
            int cin = j * 32 + i;
            word |= (unsigned)(w4[c * 768 + cin * 6 + h] >= 0.f) << i;
        }
        g_wb4t[(h * 4 + j) * 128 + c] = word ^ flip;
        return;
    }
    u -= 3072;
    if (u < 640) {
        int o = u / 64, jw = u % 64;
        unsigned word = 0;
        for (int i = 0; i < 32; i++)
            word |= (unsigned)(wf[o * 2048 + jw * 32 + i] >= 0.f) << i;
        g_wfb[u] = word;
    }
}

// Rare exact path (double, round-5 chain).
__device__ __noinline__ bool conv1_slow(const float* __restrict__ row, int L)
{
    double inv1 = g_inv1d[L], bz1 = g_bz1d[L], bb1 = g_b1d[L];
    double s0 = 0.0, s1 = 0.0;
#pragma unroll
    for (int t = 0; t < 9; t++) {
        double w = (double)g_w1s[L * 9 + t];
        s0 = fma(w, (double)row[t],     s0);
        s1 = fma(w, (double)row[t + 2], s1);
    }
    double y0 = (s0 + bb1) * inv1 + bz1;
    double y1 = (s1 + bb1) * inv1 + bz1;
    return (y0 >= 0.0) || (y1 >= 0.0);
}

// stage-C popc groups (window words Wd, channel weights wA=uint4, wC=uint2)
#define C3_S0(WD, wA, wC)  (__popc(WD[0]^wA.x)+__popc(WD[1]^wA.y)\
                           +__popc(WD[2]^wA.z)+__popc(WD[3]^wA.w)\
                           +__popc(WD[4]^wC.x)+__popc(WD[5]^wC.y))
#define C3_S1(WD, wA, wC)  (__popc(WD[2]^wA.x)+__popc(WD[3]^wA.y)\
                           +__popc(WD[4]^wA.z)+__popc(WD[5]^wA.w)\
                           +__popc(WD[6]^wC.x)+__popc(WD[7]^wC.y))
#define C3_S0H(WD, wA, wC) (__popc(WD[2]^wA.z)+__popc(WD[3]^wA.w)\
                           +__popc(WD[4]^wC.x)+__popc(WD[5]^wC.y))
#define C3_S1T(WD, wA)     (__popc(WD[2]^wA.x)+__popc(WD[3]^wA.y)\
                           +__popc(WD[4]^wA.z)+__popc(WD[5]^wA.w))

// ---------------------------------------------------------------------------
// Main fused kernel: 1 block = 1 sample, 128 threads (4 warps).
// ---------------------------------------------------------------------------
__global__ __launch_bounds__(128, 9)
void bcnn_kernel(const float* __restrict__ x, const float* __restrict__ bf,
                 float* __restrict__ out)
{
    const int b   = blockIdx.x;
    const int tid = threadIdx.x;
    const int W   = tid >> 5;
    const int L   = tid & 31;

    __shared__ __align__(16) float    xs[6 * 136];
    __shared__ __align__(16) unsigned b1s[192];
    __shared__ __align__(16) unsigned b2s[6 * 68];   // row r word k at [r*68+2+k]
    __shared__ __align__(16) unsigned b3s[384];
    __shared__ __align__(16) unsigned masks[128];

    // load sample with zero padding (4 cols each side)
    const float* xb = x + (size_t)b * 768;
    for (int i = tid; i < 768; i += 128) {
        int r = i >> 7, c = i & 127;
        xs[r * 136 + 4 + c] = xb[i];
    }
    if (tid < 48) {
        int r = tid >> 3, j = tid & 7;
        xs[r * 136 + ((j < 4) ? j : (j + 128))] = 0.f;
    }

    // ---- stage A: conv1 + bias + bn + pool(w2) + binarize ----
    float wrf[9];
#pragma unroll
    for (int t = 0; t < 9; t++) wrf[t] = g_w1s[L * 9 + t];
    float2 p1 = g_p1[L];
    __syncthreads();

    for (int pos = W; pos < 192; pos += 4) {
        int h = pos >> 5, wp = pos & 31;
        const float* row = xs + h * 136 + 4 * wp;
        const float4* rv = (const float4*)row;
        float4 v0 = rv[0], v1 = rv[1], v2 = rv[2];
        float s0, s1;
        s0 = wrf[0] * v0.x;
        s0 = __fmaf_rn(wrf[1], v0.y, s0);
        s0 = __fmaf_rn(wrf[2], v0.z, s0);
        s0 = __fmaf_rn(wrf[3], v0.w, s0);
        s0 = __fmaf_rn(wrf[4], v1.x, s0);
        s0 = __fmaf_rn(wrf[5], v1.y, s0);
        s0 = __fmaf_rn(wrf[6], v1.z, s0);
        s0 = __fmaf_rn(wrf[7], v1.w, s0);
        s0 = __fmaf_rn(wrf[8], v2.x, s0);
        s1 = wrf[0] * v0.z;
        s1 = __fmaf_rn(wrf[1], v0.w, s1);
        s1 = __fmaf_rn(wrf[2], v1.x, s1);
        s1 = __fmaf_rn(wrf[3], v1.y, s1);
        s1 = __fmaf_rn(wrf[4], v1.z, s1);
        s1 = __fmaf_rn(wrf[5], v1.w, s1);
        s1 = __fmaf_rn(wrf[6], v2.x, s1);
        s1 = __fmaf_rn(wrf[7], v2.y, s1);
        s1 = __fmaf_rn(wrf[8], v2.z, s1);
        float ym = fmaxf(__fmaf_rn(s0, p1.x, p1.y), __fmaf_rn(s1, p1.x, p1.y));
        bool bit = (ym >= 0.f);
        if (fabsf(ym) < BAND) bit = conv1_slow(row, L);
        b1s[pos] = __ballot_sync(0xffffffffu, bit);
    }
    __syncthreads();

    // ---- stage B: conv2, 3 rows interleaved (3 independent chains) ----
    {
        int q = W & 1;
        int c = q * 32 + L;
        uint4 wt = *(const uint4*)&g_wb2[c * 4];
        int2 kb = g_kB[c];
        int K96 = kb.x, K64 = kb.y;
        int r0 = 3 * (W >> 1);
        const unsigned* rp0 = b1s + r0 * 32;
        const unsigned* rp1 = rp0 + 32;
        const unsigned* rp2 = rp0 + 64;
        unsigned* o0 = b2s + r0 * 68 + 2 + q;
        unsigned* o1 = o0 + 68;
        unsigned* o2 = o0 + 136;

        uint4 A0 = *(const uint4*)rp0;
        uint4 A1 = *(const uint4*)rp1;
        uint4 A2 = *(const uint4*)rp2;
        {   // w = 0
            int s0 = __popc(A0.x ^ wt.y) + __popc(A0.y ^ wt.z);
            int s1 = __popc(A1.x ^ wt.y) + __popc(A1.y ^ wt.z);
            int s2 = __popc(A2.x ^ wt.y) + __popc(A2.y ^ wt.z);
            o0[0] = __ballot_sync(0xffffffffu, s0 <= K64);
            o1[0] = __ballot_sync(0xffffffffu, s1 <= K64);
            o2[0] = __ballot_sync(0xffffffffu, s2 <= K64);
        }
        {   // w = 1
            int s0 = __popc(A0.x ^ wt.x) + __popc(A0.y ^ wt.y) + __popc(A0.z ^ wt.z);
            int s1 = __popc(A1.x ^ wt.x) + __popc(A1.y ^ wt.y) + __popc(A1.z ^ wt.z);
            int s2 = __popc(A2.x ^ wt.x) + __popc(A2.y ^ wt.y) + __popc(A2.z ^ wt.z);
            o0[2] = __ballot_sync(0xffffffffu, s0 <= K96);
            o1[2] = __ballot_sync(0xffffffffu, s1 <= K96);
            o2[2] = __ballot_sync(0xffffffffu, s2 <= K96);
        }
        {   // w = 2
            int s0 = __popc(A0.y ^ wt.x) + __popc(A0.z ^ wt.y) + __popc(A0.w ^ wt.z);
            int s1 = __popc(A1.y ^ wt.x) + __popc(A1.z ^ wt.y) + __popc(A1.w ^ wt.z);
            int s2 = __popc(A2.y ^ wt.x) + __popc(A2.z ^ wt.y) + __popc(A2.w ^ wt.z);
            o0[4] = __ballot_sync(0xffffffffu, s0 <= K96);
            o1[4] = __ballot_sync(0xffffffffu, s1 <= K96);
            o2[4] = __ballot_sync(0xffffffffu, s2 <= K96);
        }
        unsigned p02 = A0.z, p03 = A0.w;
        unsigned p12 = A1.z, p13 = A1.w;
        unsigned p22 = A2.z, p23 = A2.w;
#pragma unroll
        for (int k = 1; k < 8; k++) {
            A0 = *(const uint4*)(rp0 + 4 * k);
            A1 = *(const uint4*)(rp1 + 4 * k);
            A2 = *(const uint4*)(rp2 + 4 * k);
            int s0, s1, s2;
            s0 = __popc(p02 ^ wt.x) + __popc(p03 ^ wt.y) + __popc(A0.x ^ wt.z);
            s1 = __popc(p12 ^ wt.x) + __popc(p13 ^ wt.y) + __popc(A1.x ^ wt.z);
            s2 = __popc(p22 ^ wt.x) + __popc(p23 ^ wt.y) + __popc(A2.x ^ wt.z);
            o0[2 * (4 * k - 1)] = __ballot_sync(0xffffffffu, s0 <= K96);
            o1[2 * (4 * k - 1)] = __ballot_sync(0xffffffffu, s1 <= K96);
            o2[2 * (4 * k - 1)] = __ballot_sync(0xffffffffu, s2 <= K96);
            s0 = __popc(p03 ^ wt.x) + __popc(A0.x ^ wt.y) + __popc(A0.y ^ wt.z);
            s1 = __popc(p13 ^ wt.x) + __popc(A1.x ^ wt.y) + __popc(A1.y ^ wt.z);
            s2 = __popc(p23 ^ wt.x) + __popc(A2.x ^ wt.y) + __popc(A2.y ^ wt.z);
            o0[2 * (4 * k)] = __ballot_sync(0xffffffffu, s0 <= K96);
            o1[2 * (4 * k)] = __ballot_sync(0xffffffffu, s1 <= K96);
            o2[2 * (4 * k)] = __ballot_sync(0xffffffffu, s2 <= K96);
            s0 = __popc(A0.x ^ wt.x) + __popc(A0.y ^ wt.y) + __popc(A0.z ^ wt.z);
            s1 = __popc(A1.x ^ wt.x) + __popc(A1.y ^ wt.y) + __popc(A1.z ^ wt.z);
            s2 = __popc(A2.x ^ wt.x) + __popc(A2.y ^ wt.y) + __popc(A2.z ^ wt.z);
            o0[2 * (4 * k + 1)] = __ballot_sync(0xffffffffu, s0 <= K96);
            o1[2 * (4 * k + 1)] = __ballot_sync(0xffffffffu, s1 <= K96);
            o2[2 * (4 * k + 1)] = __ballot_sync(0xffffffffu, s2 <= K96);
            s0 = __popc(A0.y ^ wt.x) + __popc(A0.z ^ wt.y) + __popc(A0.w ^ wt.z);
            s1 = __popc(A1.y ^ wt.x) + __popc(A1.z ^ wt.y) + __popc(A1.w ^ wt.z);
            s2 = __popc(A2.y ^ wt.x) + __popc(A2.z ^ wt.y) + __popc(A2.w ^ wt.z);
            o0[2 * (4 * k + 2)] = __ballot_sync(0xffffffffu, s0 <= K96);
            o1[2 * (4 * k + 2)] = __ballot_sync(0xffffffffu, s1 <= K96);
            o2[2 * (4 * k + 2)] = __ballot_sync(0xffffffffu, s2 <= K96);
            p02 = A0.z; p03 = A0.w;
            p12 = A1.z; p13 = A1.w;
            p22 = A2.z; p23 = A2.w;
        }
        {   // w = 31
            int s0 = __popc(p02 ^ wt.x) + __popc(p03 ^ wt.y);
            int s1 = __popc(p12 ^ wt.x) + __popc(p13 ^ wt.y);
            int s2 = __popc(p22 ^ wt.x) + __popc(p23 ^ wt.y);
            o0[62] = __ballot_sync(0xffffffffu, s0 <= K64);
            o1[62] = __ballot_sync(0xffffffffu, s1 <= K64);
            o2[62] = __ballot_sync(0xffffffffu, s2 <= K64);
        }
    }
    __syncthreads();

    // ---- stage C: conv3 + pool(w2); dual channels per lane, shared window ----
    // warps 0,1 -> rows 0..2; warps 2,3 -> rows 3..5.
    // lane L of warp with cg=(W&1) computes channels c0=cg*32+L (group cg)
    // and c1=c0+64 (group cg+2). One 12-word window serves both chains.
    {
        int cg = W & 1;
        int c0 = cg * 32 + L;
        int c1 = c0 + 64;
        uint4 wA0 = *(const uint4*)&g_wb3[c0 * 8];
        uint2 wC0 = *(const uint2*)&g_wb3[c0 * 8 + 4];
        uint4 wA1 = *(const uint4*)&g_wb3[c1 * 8];
        uint2 wC1 = *(const uint2*)&g_wb3[c1 * 8 + 4];
        int2 k0 = g_kC[c0], k1 = g_kC[c1];
        int r0 = (W >> 1) * 3;

        for (int r = r0; r < r0 + 3; r++) {
            const unsigned* rp2 = b2s + r * 68 + 2;
            unsigned* ob = b3s + r * 64;
            unsigned Wd[12];
            {
                uint2 a = *(const uint2*)(rp2 + 0);
                uint4 bq = *(const uint4*)(rp2 + 2);
                Wd[2] = a.x;  Wd[3] = a.y;
                Wd[4] = bq.x; Wd[5] = bq.y; Wd[6] = bq.z; Wd[7] = bq.w;
            }
            {
                uint4 p = *(const uint4*)(rp2 + 6);
                Wd[8] = p.x; Wd[9] = p.y; Wd[10] = p.z; Wd[11] = p.w;
            }
            {   // wp = 0: s0 has taps 1,2 (K128); s1 full (K192)
                int sa0 = C3_S0H(Wd, wA0, wC0);
                int sb0 = C3_S0H(Wd, wA1, wC1);
                int sa1 = C3_S1(Wd, wA0, wC0);
                int sb1 = C3_S1(Wd, wA1, wC1);
                bool bitA = (sa0 <= k0.y) || (sa1 <= k0.x);
                bool bitB = (sb0 <= k1.y) || (sb1 <= k1.x);
                ob[cg]     = __ballot_sync(0xffffffffu, bitA);
                ob[cg + 2] = __ballot_sync(0xffffffffu, bitB);
            }
#pragma unroll
            for (int i = 0; i < 8; i++) Wd[i] = Wd[i + 4];

#pragma unroll
            for (int wp = 1; wp < 15; wp++) {
                uint4 p = *(const uint4*)(rp2 + 4 * wp + 6);
                Wd[8] = p.x; Wd[9] = p.y; Wd[10] = p.z; Wd[11] = p.w;
                int sa0 = C3_S0(Wd, wA0, wC0);
                int sb0 = C3_S0(Wd, wA1, wC1);
                int sa1 = C3_S1(Wd, wA0, wC0);
                int sb1 = C3_S1(Wd, wA1, wC1);
                bool bitA = (sa0 <= k0.x) || (sa1 <= k0.x);
                bool bitB = (sb0 <= k1.x) || (sb1 <= k1.x);
                ob[wp * 4 + cg]     = __ballot_sync(0xffffffffu, bitA);
                ob[wp * 4 + cg + 2] = __ballot_sync(0xffffffffu, bitB);
#pragma unroll
                for (int i = 0; i < 8; i++) Wd[i] = Wd[i + 4];
            }
            {   // wp = 15: s0 full (K192); s1 has taps 0,1 (K128)
                int sa0 = C3_S0(Wd, wA0, wC0);
                int sb0 = C3_S0(Wd, wA1, wC1);
                int sa1 = C3_S1T(Wd, wA0);
                int sb1 = C3_S1T(Wd, wA1);
                bool bitA = (sa0 <= k0.x) || (sa1 <= k0.y);
                bool bitB = (sb0 <= k1.x) || (sb1 <= k1.y);
                ob[60 + cg]     = __ballot_sync(0xffffffffu, bitA);
                ob[60 + cg + 2] = __ballot_sync(0xffffffffu, bitB);
            }
        }
    }
    __syncthreads();

    // ---- stage D: conv4, coalesced transposed weights, 16 accumulators ----
    {
        int c = tid;
        int s[16];
#pragma unroll
        for (int w = 0; w < 16; w++) s[w] = 0;
#pragma unroll
        for (int h = 0; h < 6; h++) {
            const unsigned* wp4 = g_wb4t + (h * 4) * 128 + c;
            unsigned w0 = wp4[0], w1 = wp4[128], w2 = wp4[256], w3 = wp4[384];
#pragma unroll
            for (int w = 0; w < 16; w++) {
                uint4 A = *(const uint4*)&b3s[(h * 16 + w) * 4];
                s[w] += __popc(A.x ^ w0) + __popc(A.y ^ w1)
                      + __popc(A.z ^ w2) + __popc(A.w ^ w3);
            }
        }
        int K = g_kD[c];
        unsigned mask = 0;
#pragma unroll
        for (int w = 0; w < 16; w++)
            mask |= (s[w] <= K) ? (1u << w) : 0u;
        masks[c] = mask;
    }
    __syncthreads();

    // ---- stage E: fused repack + fc (10 x 2048 binary dot) + bf ----
    {
        uint2 mA = *(const uint2*)&masks[2 * L];
        uint2 mB = *(const uint2*)&masks[64 + 2 * L];
        unsigned f0 = mA.x | (mA.y << 16);
        unsigned f1 = mB.x | (mB.y << 16);
        for (int o = W; o < 10; o += 4) {
            int s = __popc(f0 ^ g_wfb[o * 64 + L])
                  + __popc(f1 ^ g_wfb[o * 64 + 32 + L]);
            int tot = __reduce_add_sync(0xffffffffu, s);
            if (L == 0) out[(size_t)b * 10 + o] = (float)(2048 - 2 * tot) + bf[o];
        }
    }
}

extern "C" void kernel_launch(void* const* d_in, const int* in_sizes, int n_in,
                              void* d_out, int out_size)
{
    const float* x   = (const float*)d_in[0];
    const float* w1  = (const float*)d_in[1];
    const float* b1  = (const float*)d_in[2];
    const float* w2  = (const float*)d_in[3];
    const float* b2  = (const float*)d_in[4];
    const float* w3  = (const float*)d_in[5];
    const float* b3  = (const float*)d_in[6];
    const float* w4  = (const float*)d_in[7];
    const float* b4  = (const float*)d_in[8];
    const float* g1  = (const float*)d_in[9];
    const float* be1 = (const float*)d_in[10];
    const float* m1  = (const float*)d_in[11];
    const float* v1  = (const float*)d_in[12];
    const float* g2  = (const float*)d_in[13];
    const float* be2 = (const float*)d_in[14];
    const float* m2  = (const float*)d_in[15];
    const float* v2  = (const float*)d_in[16];
    const float* g3  = (const float*)d_in[17];
    const float* be3 = (const float*)d_in[18];
    const float* m3  = (const float*)d_in[19];
    const float* v3  = (const float*)d_in[20];
    const float* g4  = (const float*)d_in[21];
    const float* be4 = (const float*)d_in[22];
    const float* m4  = (const float*)d_in[23];
    const float* v4  = (const float*)d_in[24];
    const float* wf  = (const float*)d_in[25];
    const float* bf  = (const float*)d_in[26];

    int B = in_sizes[0] / 768;

    prep_kernel<<<22, 256>>>(w1, b1, w2, b2, w3, b3, w4, b4,
                             g1, be1, m1, v1, g2, be2, m2, v2,
                             g3, be3, m3, v3, g4, be4, m4, v4, wf);
    bcnn_kernel<<<B, 128>>>(x, bf, (float*)d_out);
}